// round 12
// baseline (speedup 1.0000x reference)
#include <cuda_runtime.h>
#include <cuda_bf16.h>
#include <cstdint>

// Problem dims (fixed)
#define NN   8192
#define D0   128
#define D1   256
#define D2   256
#define QH   128
#define EPSV 1e-5f

// bigmm tiling: CTA 64x128, BK=32, 4 warps (warp tile 32x64), 3 stages
#define BM       64
#define BNT      128
#define BKK      32
#define NIT      (NN / BKK)              // 256
#define SA_SZ    4096                    // 64 rows * 64B  (one A matrix)
#define SB_SZ    8192                    // 128 rows * 64B (one B matrix)
#define STAGE_SZ (2 * SA_SZ + 2 * SB_SZ) // 24576
#define NSTAGE   3
#define DSMEM_MM (NSTAGE * STAGE_SZ)     // 73728 -> up to 3 CTAs/SM

// ---------------- scratch ---------------------------------------------------
__device__ float g_x[NN * QH];           // Q-hidden
__device__ float g_h[NN * D2];           // hidden (h1 then h2)
__device__ float g_part[64 * 2 * D0];
__device__ float g_scale[D0];
__device__ float g_shift[D0];
__device__ __nv_bfloat16 g_Bhi[(size_t)D1 * NN];   // Y^T hi [256, 8192]
__device__ __nv_bfloat16 g_Blo[(size_t)D1 * NN];   // Y^T lo

// ---------------- PTX helpers (baseline ISA) --------------------------------
__device__ __forceinline__ uint32_t smem_u32(const void* p) {
    uint32_t a;
    asm("{ .reg .u64 t; cvta.to.shared.u64 t, %1; cvt.u32.u64 %0, t; }" : "=r"(a) : "l"(p));
    return a;
}
__device__ __forceinline__ void cp_async16(uint32_t dst, const void* src) {
    asm volatile("cp.async.cg.shared.global [%0], [%1], 16;" :: "r"(dst), "l"(src) : "memory");
}
__device__ __forceinline__ void ldsm4(uint32_t& r0, uint32_t& r1, uint32_t& r2, uint32_t& r3,
                                      uint32_t a) {
    asm volatile("ldmatrix.sync.aligned.m8n8.x4.shared.b16 {%0,%1,%2,%3}, [%4];"
                 : "=r"(r0), "=r"(r1), "=r"(r2), "=r"(r3) : "r"(a));
}
__device__ __forceinline__ void mma_bf16(float* c, const uint32_t* a, const uint32_t* b) {
    asm volatile("mma.sync.aligned.m16n8k16.row.col.f32.bf16.bf16.f32 "
                 "{%0,%1,%2,%3}, {%4,%5,%6,%7}, {%8,%9}, {%0,%1,%2,%3};"
                 : "+f"(c[0]), "+f"(c[1]), "+f"(c[2]), "+f"(c[3])
                 : "r"(a[0]), "r"(a[1]), "r"(a[2]), "r"(a[3]), "r"(b[0]), "r"(b[1]));
}
__device__ __forceinline__ uint32_t pack_bf16x2(__nv_bfloat16 a, __nv_bfloat16 b) {
    uint16_t ua = *(uint16_t*)&a, ub = *(uint16_t*)&b;
    return (uint32_t)ua | ((uint32_t)ub << 16);
}
// swizzled 16B-chunk offset within a tile of 64B rows
__device__ __forceinline__ uint32_t swz(uint32_t row, uint32_t chunk) {
    return row * 64u + ((chunk ^ ((row >> 1) & 3u)) << 4);
}

// ---------------- batchnorm stats -> scale/shift -----------------------------
__global__ void bn_partial_kernel(const float* __restrict__ state) {
    int c = threadIdx.x, b = blockIdx.x;
    int r0 = b * (NN / 64);
    float s = 0.f, s2 = 0.f;
    #pragma unroll 4
    for (int r = 0; r < NN / 64; ++r) {
        float v = state[(size_t)(r0 + r) * D0 + c];
        s += v; s2 += v * v;
    }
    g_part[b * 2 * D0 + c]      = s;
    g_part[b * 2 * D0 + D0 + c] = s2;
}
__global__ void bn_final_kernel(const float* __restrict__ gamma,
                                const float* __restrict__ beta) {
    int c = threadIdx.x;
    float s = 0.f, s2 = 0.f;
    #pragma unroll
    for (int b = 0; b < 64; ++b) {
        s  += g_part[b * 2 * D0 + c];
        s2 += g_part[b * 2 * D0 + D0 + c];
    }
    float mean = s * (1.0f / NN);
    float var  = s2 * (1.0f / NN) - mean * mean;
    float sc = rsqrtf(var + EPSV) * gamma[c];
    g_scale[c] = sc;
    g_shift[c] = beta[c] - mean * sc;
}

// ---------------- small SGEMM, optionally: fused BN on A, split-T output ----
template<bool BIAS, bool RELU, bool DOBN, bool TOUT>
__global__ void __launch_bounds__(256)
sgemm_kernel(const float* __restrict__ A, const float* __restrict__ B,
             const float* __restrict__ bias, float* __restrict__ C,
             __nv_bfloat16* __restrict__ outHi, __nv_bfloat16* __restrict__ outLo,
             int M, int N, int K) {
    constexpr int TBM = 64, TBN = 64, TBK = 16, TM = 4, TN = 4;
    __shared__ float As[TBK][TBM];
    __shared__ float Bs[TBK][TBN];
    __shared__ uint32_t ts[TOUT ? 64 * 65 : 1];
    const int tid = threadIdx.x;
    const int tx = tid % (TBN / TN);
    const int ty = tid / (TBN / TN);
    const int rowBase = blockIdx.y * TBM;
    const int colBase = blockIdx.x * TBN;
    const int aRow = tid / (TBK / 4);
    const int aCol = (tid % (TBK / 4)) * 4;
    const int bRow = tid / (TBN / 4);
    const int bCol = (tid % (TBN / 4)) * 4;
    float acc[TM][TN] = {};
    for (int k0 = 0; k0 < K; k0 += TBK) {
        float4 av = *(const float4*)(A + (size_t)(rowBase + aRow) * K + k0 + aCol);
        if (DOBN) {
            float4 sc = *(const float4*)(g_scale + k0 + aCol);
            float4 sh = *(const float4*)(g_shift + k0 + aCol);
            av.x = fmaf(av.x, sc.x, sh.x);
            av.y = fmaf(av.y, sc.y, sh.y);
            av.z = fmaf(av.z, sc.z, sh.z);
            av.w = fmaf(av.w, sc.w, sh.w);
        }
        As[aCol + 0][aRow] = av.x; As[aCol + 1][aRow] = av.y;
        As[aCol + 2][aRow] = av.z; As[aCol + 3][aRow] = av.w;
        float4 bv = *(const float4*)(B + (size_t)(k0 + bRow) * N + colBase + bCol);
        *(float4*)&Bs[bRow][bCol] = bv;
        __syncthreads();
        #pragma unroll
        for (int k = 0; k < TBK; ++k) {
            float4 a4 = *(const float4*)&As[k][ty * TM];
            float4 b4 = *(const float4*)&Bs[k][tx * TN];
            float a[TM] = {a4.x, a4.y, a4.z, a4.w};
            float b[TN] = {b4.x, b4.y, b4.z, b4.w};
            #pragma unroll
            for (int i = 0; i < TM; ++i)
                #pragma unroll
                for (int j = 0; j < TN; ++j)
                    acc[i][j] = fmaf(a[i], b[j], acc[i][j]);
        }
        __syncthreads();
    }

    if (!TOUT) {
        #pragma unroll
        for (int i = 0; i < TM; ++i) {
            int r = rowBase + ty * TM + i;
            #pragma unroll
            for (int j = 0; j < TN; ++j) {
                int c = colBase + tx * TN + j;
                float v = acc[i][j];
                if (BIAS) v += bias[c];
                if (RELU) v = fmaxf(v, 0.f);
                C[(size_t)r * N + c] = v;
            }
        }
    } else {
        #pragma unroll
        for (int i = 0; i < TM; ++i)
            #pragma unroll
            for (int j = 0; j < TN; ++j) {
                int cl = tx * TN + j, rl = ty * TM + i;
                float v = acc[i][j];
                __nv_bfloat16 hi = __float2bfloat16(v);
                __nv_bfloat16 lo = __float2bfloat16(v - __bfloat162float(hi));
                ts[cl * 65 + rl] = pack_bf16x2(hi, lo);
            }
        __syncthreads();
        #pragma unroll
        for (int i = 0; i < 8; ++i) {
            int id = i * 256 + tid;
            int cl = id >> 5, rp = (id & 31) * 2;
            uint32_t v0 = ts[cl * 65 + rp], v1 = ts[cl * 65 + rp + 1];
            uint32_t hh = (v0 & 0xFFFFu) | (v1 << 16);
            uint32_t ll = (v0 >> 16) | (v1 & 0xFFFF0000u);
            size_t o = (size_t)(colBase + cl) * NN + rowBase + rp;
            *(uint32_t*)(outHi + o) = hh;
            *(uint32_t*)(outLo + o) = ll;
        }
    }
}

// ---------------- big GEMM: C = relu(A_fp32 @ B^T + bias) --------------------
// A fp32 [NN,NN] row-major, split bf16 hi/lo in-kernel.  B hi/lo [256,NN] K-major.
// CTA tile 64x128xK32; 4 warps, warp tile 32x64 (B fragments reused 8x);
// 3-stage swizzled cp.async pipeline; up to 3 CTAs/SM.
__global__ void __launch_bounds__(128, 3)
bigmm_kernel(const float* __restrict__ A,
             const __nv_bfloat16* __restrict__ Bhi, const __nv_bfloat16* __restrict__ Blo,
             const float* __restrict__ bias, float* __restrict__ C) {
    extern __shared__ char sm[];
    const uint32_t sbase = smem_u32(sm);
    const int tid = threadIdx.x;           // 0..127
    const int n0 = blockIdx.x * BNT;
    const int m0 = blockIdx.y * BM;

    // ---- loaders ----
    // A: 2 threads per row, 16 floats (64B) each
    const int arow = tid >> 1, ahalf = tid & 1;
    const float* gA = A + (size_t)(m0 + arow) * NN + ahalf * 16;
    // B: 1 thread per row (128 rows), 64B per row per matrix
    const __nv_bfloat16* gBh = Bhi + (size_t)(n0 + tid) * NN;
    const __nv_bfloat16* gBl = Blo + (size_t)(n0 + tid) * NN;

    float4 rA[4];
    auto LDG_A = [&](int j) {
        const float* p = gA + (size_t)j * BKK;
        rA[0] = *(const float4*)(p + 0);
        rA[1] = *(const float4*)(p + 4);
        rA[2] = *(const float4*)(p + 8);
        rA[3] = *(const float4*)(p + 12);
    };
    auto STS_A = [&](int s) {
        const float* f = (const float*)rA;
        uint32_t hbuf[8], lbuf[8];
        #pragma unroll
        for (int e = 0; e < 8; ++e) {
            float x0 = f[2 * e], x1 = f[2 * e + 1];
            __nv_bfloat16 h0 = __float2bfloat16(x0);
            __nv_bfloat16 h1 = __float2bfloat16(x1);
            __nv_bfloat16 l0 = __float2bfloat16(x0 - __bfloat162float(h0));
            __nv_bfloat16 l1 = __float2bfloat16(x1 - __bfloat162float(h1));
            hbuf[e] = pack_bf16x2(h0, h1);
            lbuf[e] = pack_bf16x2(l0, l1);
        }
        char* base = sm + s * STAGE_SZ;
        *(uint4*)(base + swz(arow, ahalf * 2))             = *(uint4*)&hbuf[0];
        *(uint4*)(base + swz(arow, ahalf * 2 + 1))         = *(uint4*)&hbuf[4];
        *(uint4*)(base + SA_SZ + swz(arow, ahalf * 2))     = *(uint4*)&lbuf[0];
        *(uint4*)(base + SA_SZ + swz(arow, ahalf * 2 + 1)) = *(uint4*)&lbuf[4];
    };
    auto CP_B = [&](int s, int j) {
        uint32_t sb = sbase + s * STAGE_SZ + 2 * SA_SZ;
        size_t k = (size_t)j * BKK;
        #pragma unroll
        for (int c = 0; c < 4; ++c) {
            uint32_t d = sb + swz(tid, c);
            cp_async16(d,         gBh + k + c * 8);
            cp_async16(d + SB_SZ, gBl + k + c * 8);
        }
        asm volatile("cp.async.commit_group;" ::: "memory");
    };

    // ---- compute mapping: 4 warps = 2(m) x 2(n), warp tile 32x64 ----
    const int wid = tid >> 5, lane = tid & 31;
    const int wm = wid & 1, wn = wid >> 1;
    const uint32_t rowA0 = wm * 32 + (lane & 15);
    const uint32_t ca    = lane >> 4;               // 0/1
    const uint32_t rowB0 = wn * 64 + ((lane >> 4) << 3) + (lane & 7);
    const uint32_t cb    = (lane >> 3) & 1;

    float acc[2][8][4];
    #pragma unroll
    for (int mt = 0; mt < 2; ++mt)
        #pragma unroll
        for (int nt = 0; nt < 8; ++nt)
            #pragma unroll
            for (int e = 0; e < 4; ++e) acc[mt][nt][e] = 0.f;

    // ---- prologue ----
    LDG_A(0); STS_A(0); CP_B(0, 0);
    LDG_A(1); STS_A(1); CP_B(1, 1);
    LDG_A(2);

    for (int j = 0; j < NIT; ++j) {
        if (j + 2 < NIT) {
            asm volatile("cp.async.wait_group 1;" ::: "memory");
        } else {
            asm volatile("cp.async.wait_group 0;" ::: "memory");
        }
        __syncthreads();
        if (j + 2 < NIT) {
            const int ls = (j + 2) % NSTAGE;
            STS_A(ls);                 // rA holds data for iteration j+2
            CP_B(ls, j + 2);
        }
        if (j + 3 < NIT) LDG_A(j + 3);

        const uint32_t sb  = sbase + (j % NSTAGE) * STAGE_SZ;
        const uint32_t sbB = sb + 2 * SA_SZ;
        #pragma unroll
        for (int kh = 0; kh < 2; ++kh) {
            uint32_t ah[2][4], al[2][4], bh[8][2], bl[8][2];
            #pragma unroll
            for (int mt = 0; mt < 2; ++mt) {
                uint32_t ad = sb + swz(rowA0 + mt * 16, kh * 2 + ca);
                ldsm4(ah[mt][0], ah[mt][1], ah[mt][2], ah[mt][3], ad);
                ldsm4(al[mt][0], al[mt][1], al[mt][2], al[mt][3], ad + SA_SZ);
            }
            #pragma unroll
            for (int p = 0; p < 4; ++p) {
                uint32_t bd = sbB + swz(rowB0 + p * 16, kh * 2 + cb);
                uint32_t r0, r1, r2, r3;
                ldsm4(r0, r1, r2, r3, bd);
                bh[2 * p][0] = r0; bh[2 * p][1] = r1;
                bh[2 * p + 1][0] = r2; bh[2 * p + 1][1] = r3;
                ldsm4(r0, r1, r2, r3, bd + SB_SZ);
                bl[2 * p][0] = r0; bl[2 * p][1] = r1;
                bl[2 * p + 1][0] = r2; bl[2 * p + 1][1] = r3;
            }
            #pragma unroll
            for (int mt = 0; mt < 2; ++mt)
                #pragma unroll
                for (int nt = 0; nt < 8; ++nt)
                    mma_bf16(acc[mt][nt], ah[mt], bh[nt]);
            #pragma unroll
            for (int mt = 0; mt < 2; ++mt)
                #pragma unroll
                for (int nt = 0; nt < 8; ++nt)
                    mma_bf16(acc[mt][nt], al[mt], bh[nt]);
            #pragma unroll
            for (int mt = 0; mt < 2; ++mt)
                #pragma unroll
                for (int nt = 0; nt < 8; ++nt)
                    mma_bf16(acc[mt][nt], ah[mt], bl[nt]);
        }
    }

    // ---- epilogue: bias + relu + store ----
    #pragma unroll
    for (int mt = 0; mt < 2; ++mt) {
        #pragma unroll
        for (int nt = 0; nt < 8; ++nt) {
            int r = m0 + wm * 32 + mt * 16 + (lane >> 2);
            int c = n0 + wn * 64 + nt * 8 + (lane & 3) * 2;
            float b0 = bias[c], b1 = bias[c + 1];
            float2 v0;
            v0.x = fmaxf(acc[mt][nt][0] + b0, 0.f);
            v0.y = fmaxf(acc[mt][nt][1] + b1, 0.f);
            *(float2*)(C + (size_t)r * 256 + c) = v0;
            float2 v1;
            v1.x = fmaxf(acc[mt][nt][2] + b0, 0.f);
            v1.y = fmaxf(acc[mt][nt][3] + b1, 0.f);
            *(float2*)(C + (size_t)(r + 8) * 256 + c) = v1;
        }
    }
}

// ---------------- final Q output --------------------------------------------
__global__ void qout_kernel(const float* __restrict__ T,
                            const float* __restrict__ Wq2,
                            const float* __restrict__ bq2,
                            float* __restrict__ out) {
    int warp = threadIdx.x >> 5;
    int lane = threadIdx.x & 31;
    int row  = blockIdx.x * 8 + warp;
    const float* t = T + (size_t)row * QH;
    float s = 0.f;
    #pragma unroll
    for (int k = lane; k < QH; k += 32) s += t[k] * Wq2[k];
    #pragma unroll
    for (int o = 16; o; o >>= 1) s += __shfl_xor_sync(0xffffffffu, s, o);
    if (lane == 0) out[row] = s + bq2[0];
}

// ---------------- launcher --------------------------------------------------
extern "C" void kernel_launch(void* const* d_in, const int* in_sizes, int n_in,
                              void* d_out, int out_size) {
    const float* state = (const float*)d_in[0];
    const float* adj   = (const float*)d_in[1];
    const float* gamma = (const float*)d_in[2];
    const float* beta  = (const float*)d_in[3];
    const float* W1    = (const float*)d_in[4];
    const float* b1    = (const float*)d_in[5];
    const float* W2    = (const float*)d_in[6];
    const float* b2    = (const float*)d_in[7];
    const float* Wq1   = (const float*)d_in[8];
    const float* bq1   = (const float*)d_in[9];
    const float* Wq2   = (const float*)d_in[10];
    const float* bq2   = (const float*)d_in[11];
    float* out = (float*)d_out;

    float *gx, *gh;
    cudaGetSymbolAddress((void**)&gx, g_x);
    cudaGetSymbolAddress((void**)&gh, g_h);
    __nv_bfloat16 *gBhi, *gBlo;
    cudaGetSymbolAddress((void**)&gBhi, g_Bhi);
    cudaGetSymbolAddress((void**)&gBlo, g_Blo);

    cudaFuncSetAttribute(bigmm_kernel, cudaFuncAttributeMaxDynamicSharedMemorySize, DSMEM_MM);

    // BatchNorm stats -> scale/shift
    bn_partial_kernel<<<64, D0>>>(state);
    bn_final_kernel<<<1, D0>>>(gamma, beta);

    // Y1^T(hi/lo) = split_T(bn(state) @ W1)
    sgemm_kernel<false, false, true, true>
        <<<dim3(D1 / 64, NN / 64), 256>>>(state, W1, nullptr, nullptr, gBhi, gBlo, NN, D1, D0);

    // h1 = relu(A @ Y1 + b1)
    bigmm_kernel<<<dim3(2, NN / BM), 128, DSMEM_MM>>>(adj, gBhi, gBlo, b1, gh);

    // Y2^T(hi/lo) = split_T(h1 @ W2)
    sgemm_kernel<false, false, false, true>
        <<<dim3(D2 / 64, NN / 64), 256>>>(gh, W2, nullptr, nullptr, gBhi, gBlo, NN, D2, D1);

    // h2 = relu(A @ Y2 + b2)
    bigmm_kernel<<<dim3(2, NN / BM), 128, DSMEM_MM>>>(adj, gBhi, gBlo, b2, gh);

    // Q head
    sgemm_kernel<true, true, false, false>
        <<<dim3(QH / 64, NN / 64), 256>>>(gh, Wq1, bq1, gx, nullptr, nullptr, NN, QH, D2);
    qout_kernel<<<NN / 8, 256>>>(gx, Wq2, bq2, out);
}